// round 7
// baseline (speedup 1.0000x reference)
#include <cuda_runtime.h>

#define TSEQ  128
#define BATCH 4096

// Inter-layer sequence scratch (static device globals; no allocation anywhere).
// L3 output aliases the front of d_seq1 (seq1 is dead once L2 finished reading it).
__device__ float d_seq1[(size_t)BATCH * TSEQ * 128]; // L1 out [B,T,128]; front reused as L3 out [B,T,32]
__device__ float d_seq2[(size_t)BATCH * TSEQ * 64];  // L2 out [B,T,64]
__device__ float d_h4[BATCH * 8];                    // L4 final states [B,8]

__device__ __forceinline__ float fsig(float x) {
    return 1.0f / (1.0f + __expf(-x));
}
__device__ __forceinline__ float ftanh(float x) {
    // 1 - 2/(e^{2x}+1): saturates cleanly at +/-1, no inf/inf
    float e = __expf(2.0f * x);
    return 1.0f - 2.0f / (e + 1.0f);
}

// Buffer tags: 0 = kernel param, 1 = d_seq1, 2 = d_seq2, 3 = d_seq1 (as L3 out)
template<int TAG>
__device__ __forceinline__ float* buf_ptr(float* param) {
    if (TAG == 1 || TAG == 3) return d_seq1;
    if (TAG == 2) return d_seq2;
    return param;
}

// Fused bidirectional LSTM layer (layers 1-3).
//   grid = (BATCH/BT, 2)  [y: 0=forward, 1=backward], 512 threads.
//   Thread (tj, tb): 8 gate columns (2 hidden units x 4 gates) for BPT batch rows.
//   Weights permuted in smem to [k][jh*4+gate] (two LDS.128 per k).
//   sX and sH are DOUBLE-BUFFERED -> one __syncthreads per step. Next-step x is
//   LDG'd into registers before the GEMM and STS'd after it, hiding gmem latency
//   under the FMA work.
template<int D, int H, int BT, int BPT, int SRC, int DST>
__global__ void __launch_bounds__((H / 2) * (BT / BPT))
lstm_layer(float* __restrict__ in_param, float* __restrict__ out_param,
           const float* __restrict__ WkF, const float* __restrict__ WrF, const float* __restrict__ bF,
           const float* __restrict__ WkB, const float* __restrict__ WrB, const float* __restrict__ bB)
{
    constexpr int NG = 4 * H;
    constexpr int TJ = NG / 8;       // threads along j (= H/2)
    constexpr int TB = BT / BPT;     // threads along batch
    constexpr int NT = TJ * TB;      // 512 for all instantiations
    constexpr int DS = (D % 2 == 0) ? D + 1 : D;  // padded strides (bank conflicts)
    constexpr int HS = H + 1;
    constexpr int XCNT = (BT * D + NT - 1) / NT;  // staged x elems per thread

    const float* in = buf_ptr<SRC>(in_param);
    float* out = buf_ptr<DST>(out_param);

    extern __shared__ float sm[];
    float* sWk = sm;                 // [D][NG] permuted
    float* sWr = sWk + D * NG;       // [H][NG] permuted
    float* sB  = sWr + H * NG;       // [NG]    permuted
    float* sH  = sB + NG;            // 2 x [BT][HS]
    float* sX  = sH + 2 * BT * HS;   // 2 x [BT][DS]

    const int tid = threadIdx.x;
    const int tj  = tid % TJ;
    const int tb  = tid / TJ;
    const bool fwd = (blockIdx.y == 0);
    const float* Wk = fwd ? WkF : WkB;
    const float* Wr = fwd ? WrF : WrB;
    const float* bv = fwd ? bF  : bB;
    const int b0 = blockIdx.x * BT;

    // Load + permute weights: new col = jh*4+g  <-  old col = g*H+jh
    for (int i = tid; i < D * NG; i += NT) {
        int k = i / NG, col = i - k * NG;
        sWk[i] = Wk[k * NG + (col & 3) * H + (col >> 2)];
    }
    for (int i = tid; i < H * NG; i += NT) {
        int k = i / NG, col = i - k * NG;
        sWr[i] = Wr[k * NG + (col & 3) * H + (col >> 2)];
    }
    for (int i = tid; i < NG; i += NT)
        sB[i] = bv[(i & 3) * H + (i >> 2)];
    for (int i = tid; i < 2 * BT * HS; i += NT) sH[i] = 0.0f;

    // stage x_{t0} into buffer 0
    {
        const int t0 = fwd ? 0 : (TSEQ - 1);
        const float* inb = in + ((size_t)b0 * TSEQ + t0) * D;
        for (int i = tid; i < BT * D; i += NT) {
            int b = i / D, k = i - b * D;
            sX[b * DS + k] = inb[(size_t)b * TSEQ * D + k];
        }
    }
    __syncthreads();

    float bj[8];
#pragma unroll
    for (int q = 0; q < 8; q++) bj[q] = sB[tj * 8 + q];

    float cst[BPT][2];
#pragma unroll
    for (int bi = 0; bi < BPT; bi++) { cst[bi][0] = 0.0f; cst[bi][1] = 0.0f; }

    const int jh0 = tj * 2;
    const float* wk = sWk + tj * 8;
    const float* wr = sWr + tj * 8;

    for (int s = 0; s < TSEQ; s++) {
        const int t   = fwd ? s : (TSEQ - 1 - s);
        const int cur = s & 1;
        const int nxt = cur ^ 1;
        const float* sXc = sX + cur * BT * DS;
        const float* sHc = sH + cur * BT * HS;

        // issue next-step x LDGs early; latency hides under the GEMM below
        float xreg[XCNT];
        const bool have_next = (s + 1 < TSEQ);
        if (have_next) {
            const int tn = fwd ? (s + 1) : (TSEQ - 2 - s);
            const float* inb = in + ((size_t)b0 * TSEQ + tn) * D;
            int c = 0;
            for (int i = tid; i < BT * D; i += NT, c++) {
                int b = i / D, k = i - b * D;
                xreg[c] = inb[(size_t)b * TSEQ * D + k];
            }
        }

        float acc[BPT][8];
#pragma unroll
        for (int bi = 0; bi < BPT; bi++)
#pragma unroll
            for (int q = 0; q < 8; q++) acc[bi][q] = bj[q];

        // z += x_t @ Wk
#pragma unroll 4
        for (int k = 0; k < D; k++) {
            float4 w0 = *(const float4*)(wk + k * NG);
            float4 w1 = *(const float4*)(wk + k * NG + 4);
#pragma unroll
            for (int bi = 0; bi < BPT; bi++) {
                float v = sXc[(tb * BPT + bi) * DS + k];
                acc[bi][0] = fmaf(v, w0.x, acc[bi][0]);
                acc[bi][1] = fmaf(v, w0.y, acc[bi][1]);
                acc[bi][2] = fmaf(v, w0.z, acc[bi][2]);
                acc[bi][3] = fmaf(v, w0.w, acc[bi][3]);
                acc[bi][4] = fmaf(v, w1.x, acc[bi][4]);
                acc[bi][5] = fmaf(v, w1.y, acc[bi][5]);
                acc[bi][6] = fmaf(v, w1.z, acc[bi][6]);
                acc[bi][7] = fmaf(v, w1.w, acc[bi][7]);
            }
        }
        // z += h_{t-1} @ Wr
#pragma unroll 4
        for (int k = 0; k < H; k++) {
            float4 w0 = *(const float4*)(wr + k * NG);
            float4 w1 = *(const float4*)(wr + k * NG + 4);
#pragma unroll
            for (int bi = 0; bi < BPT; bi++) {
                float v = sHc[(tb * BPT + bi) * HS + k];
                acc[bi][0] = fmaf(v, w0.x, acc[bi][0]);
                acc[bi][1] = fmaf(v, w0.y, acc[bi][1]);
                acc[bi][2] = fmaf(v, w0.z, acc[bi][2]);
                acc[bi][3] = fmaf(v, w0.w, acc[bi][3]);
                acc[bi][4] = fmaf(v, w1.x, acc[bi][4]);
                acc[bi][5] = fmaf(v, w1.y, acc[bi][5]);
                acc[bi][6] = fmaf(v, w1.z, acc[bi][6]);
                acc[bi][7] = fmaf(v, w1.w, acc[bi][7]);
            }
        }

        // drain staged x into the next buffer (no one reads sX[nxt] this step)
        if (have_next) {
            float* sXn = sX + nxt * BT * DS;
            int c = 0;
            for (int i = tid; i < BT * D; i += NT, c++) {
                int b = i / D, k = i - b * D;
                sXn[b * DS + k] = xreg[c];
            }
        }

        // gates: [i, f, g, o] per hidden unit; c in regs, h -> sH[nxt] + out
        {
            float* sHn = sH + nxt * BT * HS;
#pragma unroll
            for (int bi = 0; bi < BPT; bi++) {
                const int b = tb * BPT + bi;
                float h2[2];
#pragma unroll
                for (int jj = 0; jj < 2; jj++) {
                    float zi = acc[bi][jj * 4 + 0];
                    float zf = acc[bi][jj * 4 + 1];
                    float zg = acc[bi][jj * 4 + 2];
                    float zo = acc[bi][jj * 4 + 3];
                    float cc = fsig(zf) * cst[bi][jj] + fsig(zi) * ftanh(zg);
                    cst[bi][jj] = cc;
                    h2[jj] = fsig(zo) * ftanh(cc);
                    sHn[b * HS + jh0 + jj] = h2[jj];
                }
                float2 hv = make_float2(h2[0], h2[1]);
                *(float2*)(out + ((size_t)(b0 + b) * TSEQ + t) * (2 * H)
                               + (fwd ? 0 : H) + jh0) = hv;
            }
        }
        __syncthreads();   // single barrier: everything published for step s+1
    }
}

// Layer 4 (D=32, H=4, return final state only).
// 4 threads per (row, direction): thread handles ONE hidden unit (4 gate cols).
// h exchanged across the lane-quad with __shfl_sync; c scalar in register.
// x double-buffered in registers. No __syncthreads in the time loop.
__global__ void __launch_bounds__(128)
lstm_l4(const float* __restrict__ WkF, const float* __restrict__ WrF, const float* __restrict__ bF,
        const float* __restrict__ WkB, const float* __restrict__ WrB, const float* __restrict__ bB)
{
    const float* in = d_seq1;        // L3 output, [B][T][32]
    const int tid  = threadIdx.x;
    const int unit = tid & 3;
    const int rl   = tid >> 2;       // 0..31
    const int lane = tid & 31;
    const bool fwd = (blockIdx.y == 0);
    const int row  = blockIdx.x * 32 + rl;

    __shared__ alignas(16) float sWk[32 * 16];   // permuted [k][j*4+g]
    __shared__ alignas(16) float sWr[4 * 16];
    __shared__ alignas(16) float sB[16];

    const float* Wk = fwd ? WkF : WkB;
    const float* Wr = fwd ? WrF : WrB;
    const float* bv = fwd ? bF  : bB;

    for (int i = tid; i < 32 * 16; i += 128) {
        int k = i >> 4, col = i & 15;
        sWk[i] = Wk[k * 16 + (col & 3) * 4 + (col >> 2)];
    }
    if (tid < 4 * 16) {
        int k = tid >> 4, col = tid & 15;
        sWr[tid] = Wr[k * 16 + (col & 3) * 4 + (col >> 2)];
    }
    if (tid < 16) sB[tid] = bv[(tid & 3) * 4 + (tid >> 2)];
    __syncthreads();

    float bz[4];
#pragma unroll
    for (int q = 0; q < 4; q++) bz[q] = sB[unit * 4 + q];

    float h = 0.0f, c = 0.0f;

    const float* base = in + (size_t)row * TSEQ * 32;
    float4 xa[8], xb[8];
    {
        const float4* p = (const float4*)(base + (fwd ? 0 : (TSEQ - 1)) * 32);
#pragma unroll
        for (int i = 0; i < 8; i++) xa[i] = p[i];
    }

#pragma unroll 1
    for (int s = 0; s < TSEQ; s++) {
        if (s + 1 < TSEQ) {
            const int tn = fwd ? (s + 1) : (TSEQ - 2 - s);
            const float4* p = (const float4*)(base + tn * 32);
#pragma unroll
            for (int i = 0; i < 8; i++) xb[i] = p[i];
        }

        float z[4];
#pragma unroll
        for (int q = 0; q < 4; q++) z[q] = bz[q];

#pragma unroll
        for (int k = 0; k < 32; k++) {
            float v = ((const float*)xa)[k];
            float4 w = *(const float4*)(sWk + k * 16 + unit * 4);
            z[0] = fmaf(v, w.x, z[0]);
            z[1] = fmaf(v, w.y, z[1]);
            z[2] = fmaf(v, w.z, z[2]);
            z[3] = fmaf(v, w.w, z[3]);
        }
#pragma unroll
        for (int k = 0; k < 4; k++) {
            float hk = __shfl_sync(0xffffffffu, h, (lane & ~3) + k, 32);
            float4 w = *(const float4*)(sWr + k * 16 + unit * 4);
            z[0] = fmaf(hk, w.x, z[0]);
            z[1] = fmaf(hk, w.y, z[1]);
            z[2] = fmaf(hk, w.z, z[2]);
            z[3] = fmaf(hk, w.w, z[3]);
        }

        float cc = fsig(z[1]) * c + fsig(z[0]) * ftanh(z[2]);
        c = cc;
        h = fsig(z[3]) * ftanh(cc);

#pragma unroll
        for (int i = 0; i < 8; i++) xa[i] = xb[i];
    }

    d_h4[(size_t)row * 8 + (fwd ? 0 : 4) + unit] = h;
}

__global__ void dense_sig(const float* __restrict__ W,
                          const float* __restrict__ bb, float* __restrict__ out)
{
    int b = blockIdx.x * blockDim.x + threadIdx.x;
    if (b >= BATCH) return;
    const float* hr = d_h4 + (size_t)b * 8;
    float hv[8];
#pragma unroll
    for (int j = 0; j < 8; j++) hv[j] = hr[j];
#pragma unroll
    for (int m = 0; m < 3; m++) {
        float a = bb[m];
#pragma unroll
        for (int j = 0; j < 8; j++) a = fmaf(hv[j], W[j * 3 + m], a);
        out[(size_t)b * 3 + m] = fsig(a);
    }
}

static size_t smem_bytes(int D, int H, int BT) {
    int NG = 4 * H;
    int DS = (D % 2 == 0) ? D + 1 : D;
    int HS = H + 1;
    return (size_t)(D * NG + H * NG + NG + 2 * BT * HS + 2 * BT * DS) * sizeof(float);
}

extern "C" void kernel_launch(void* const* d_in, const int* in_sizes, int n_in,
                              void* d_out, int out_size)
{
    (void)in_sizes; (void)n_in; (void)out_size;
    float* x = (float*)d_in[0];
    const float* p[24];
    for (int i = 0; i < 24; i++) p[i] = (const float*)d_in[1 + i];
    const float* dW = (const float*)d_in[25];
    const float* db = (const float*)d_in[26];

    size_t s1 = smem_bytes(78, 64, 64);
    size_t s2 = smem_bytes(128, 32, 64);
    size_t s3 = smem_bytes(64, 16, 64);
    cudaFuncSetAttribute(lstm_layer<78, 64, 64, 4, 0, 1>,
                         cudaFuncAttributeMaxDynamicSharedMemorySize, (int)s1);
    cudaFuncSetAttribute(lstm_layer<128, 32, 64, 2, 1, 2>,
                         cudaFuncAttributeMaxDynamicSharedMemorySize, (int)s2);
    cudaFuncSetAttribute(lstm_layer<64, 16, 64, 1, 2, 3>,
                         cudaFuncAttributeMaxDynamicSharedMemorySize, (int)s3);

    // L1: x -> seq1 (78 -> 2*64), grid (64,2), 512 thr
    lstm_layer<78, 64, 64, 4, 0, 1><<<dim3(BATCH / 64, 2), 512, s1>>>(
        x, nullptr, p[0], p[1], p[2], p[3], p[4], p[5]);
    // L2: seq1 -> seq2 (128 -> 2*32), 512 thr
    lstm_layer<128, 32, 64, 2, 1, 2><<<dim3(BATCH / 64, 2), 512, s2>>>(
        nullptr, nullptr, p[6], p[7], p[8], p[9], p[10], p[11]);
    // L3: seq2 -> seq3(=seq1 front) (64 -> 2*16), 512 thr
    lstm_layer<64, 16, 64, 1, 2, 3><<<dim3(BATCH / 64, 2), 512, s3>>>(
        nullptr, nullptr, p[12], p[13], p[14], p[15], p[16], p[17]);
    // L4: seq3 -> h4 final states [B,8], 4 threads/row, shuffle-coupled
    lstm_l4<<<dim3(BATCH / 32, 2), 128>>>(p[18], p[19], p[20], p[21], p[22], p[23]);
    // dense 8->3 + sigmoid
    dense_sig<<<(BATCH + 255) / 256, 256>>>(dW, db, (float*)d_out);
}

// round 8
// speedup vs baseline: 1.4706x; 1.4706x over previous
#include <cuda_runtime.h>

#define TSEQ  128
#define BATCH 4096

// Inter-layer sequence scratch (static device globals; no allocation anywhere).
// L3 output aliases the front of d_seq1 (seq1 is dead once L2 finished reading it).
__device__ float d_seq1[(size_t)BATCH * TSEQ * 128]; // L1 out [B,T,128]; front reused as L3 out [B,T,32]
__device__ float d_seq2[(size_t)BATCH * TSEQ * 64];  // L2 out [B,T,64]
__device__ float d_h4[BATCH * 8];                    // L4 final states [B,8]

__device__ __forceinline__ float fsig(float x) {
    return 1.0f / (1.0f + __expf(-x));
}
__device__ __forceinline__ float ftanh(float x) {
    // 1 - 2/(e^{2x}+1): saturates cleanly at +/-1, no inf/inf
    float e = __expf(2.0f * x);
    return 1.0f - 2.0f / (e + 1.0f);
}

// Buffer tags: 0 = kernel param, 1 = d_seq1, 2 = d_seq2, 3 = d_seq1 (as L3 out)
template<int TAG>
__device__ __forceinline__ float* buf_ptr(float* param) {
    if (TAG == 1 || TAG == 3) return d_seq1;
    if (TAG == 2) return d_seq2;
    return param;
}

// Fused bidirectional LSTM layer (layers 1-3). R5-proven GEMM core (256 thr,
// BPT=8/4/2) plus: (a) staging indices hoisted out of the time loop (no per-step
// integer division), (b) sX/sH double-buffered -> ONE __syncthreads per step,
// next-step x LDG'd into registers at step top and drained via STS after the
// GEMM so gmem latency hides under the FMA work.
template<int D, int H, int BT, int BPT, int SRC, int DST>
__global__ void __launch_bounds__((H / 2) * (BT / BPT))
lstm_layer(float* __restrict__ in_param, float* __restrict__ out_param,
           const float* __restrict__ WkF, const float* __restrict__ WrF, const float* __restrict__ bF,
           const float* __restrict__ WkB, const float* __restrict__ WrB, const float* __restrict__ bB)
{
    constexpr int NG = 4 * H;
    constexpr int TJ = NG / 8;       // threads along j (= H/2)
    constexpr int TB = BT / BPT;     // threads along batch
    constexpr int NT = TJ * TB;      // 256 for all instantiations
    constexpr int DS = (D % 2 == 0) ? D + 1 : D;  // padded stride
    constexpr int HS = H + 1;
    constexpr int XCNT = (BT * D + NT - 1) / NT;  // staged x elems per thread
    constexpr bool DIVD = (NT % D) == 0;          // strided index form available

    const float* in = buf_ptr<SRC>(in_param);
    float* out = buf_ptr<DST>(out_param);

    extern __shared__ float sm[];
    float* sWk = sm;                 // [D][NG] permuted
    float* sWr = sWk + D * NG;       // [H][NG] permuted
    float* sB  = sWr + H * NG;       // [NG]    permuted
    float* sH  = sB + NG;            // 2 x [BT][HS]
    float* sX  = sH + 2 * BT * HS;   // 2 x [BT][DS]

    const int tid = threadIdx.x;
    const int tj  = tid % TJ;
    const int tb  = tid / TJ;
    const bool fwd = (blockIdx.y == 0);
    const float* Wk = fwd ? WkF : WkB;
    const float* Wr = fwd ? WrF : WrB;
    const float* bv = fwd ? bF  : bB;
    const int b0 = blockIdx.x * BT;
    const float* inb0 = in + (size_t)b0 * TSEQ * D;

    // ---- hoisted staging indices (step-invariant) ----
    // element i = tid + c*NT -> (b = i/D, k = i%D); gmem off = b*TSEQ*D + k,
    // smem off = b*DS + k.
    int goff[XCNT], soff[XCNT];
    int NC;
    if (DIVD) {
        // b = tid/D + c*(NT/D), k = tid%D : pure stride in c
        const int bb = tid / D, kk = tid - bb * D;
        NC = XCNT;  // BT*D divisible by NT in these instantiations
#pragma unroll
        for (int c = 0; c < XCNT; c++) {
            goff[c] = (bb + c * (NT / D)) * TSEQ * D + kk;
            soff[c] = (bb + c * (NT / D)) * DS + kk;
        }
    } else {
        NC = 0;
#pragma unroll
        for (int c = 0; c < XCNT; c++) {
            int i = tid + c * NT;
            if (i < BT * D) {
                int b = i / D, k = i - b * D;
                goff[c] = b * TSEQ * D + k;
                soff[c] = b * DS + k;
                NC++;
            }
        }
    }

    // Load + permute weights: new col = jh*4+g  <-  old col = g*H+jh
    for (int i = tid; i < D * NG; i += NT) {
        int k = i / NG, col = i - k * NG;
        sWk[i] = Wk[k * NG + (col & 3) * H + (col >> 2)];
    }
    for (int i = tid; i < H * NG; i += NT) {
        int k = i / NG, col = i - k * NG;
        sWr[i] = Wr[k * NG + (col & 3) * H + (col >> 2)];
    }
    for (int i = tid; i < NG; i += NT)
        sB[i] = bv[(i & 3) * H + (i >> 2)];
    for (int i = tid; i < 2 * BT * HS; i += NT) sH[i] = 0.0f;

    // stage x_{t0} into buffer 0
    {
        const int t0 = fwd ? 0 : (TSEQ - 1);
        const float* inb = inb0 + (size_t)t0 * D;
#pragma unroll
        for (int c = 0; c < XCNT; c++)
            if (c < NC) sX[soff[c]] = inb[goff[c]];
    }
    __syncthreads();

    float bj[8];
#pragma unroll
    for (int q = 0; q < 8; q++) bj[q] = sB[tj * 8 + q];

    float cst[BPT][2];
#pragma unroll
    for (int bi = 0; bi < BPT; bi++) { cst[bi][0] = 0.0f; cst[bi][1] = 0.0f; }

    const int jh0 = tj * 2;
    const float* wk = sWk + tj * 8;
    const float* wr = sWr + tj * 8;

    for (int s = 0; s < TSEQ; s++) {
        const int t   = fwd ? s : (TSEQ - 1 - s);
        const int cur = s & 1;
        const int nxt = cur ^ 1;
        const float* sXc = sX + cur * BT * DS;
        const float* sHc = sH + cur * BT * HS;

        // issue next-step x LDGs; latency hides under the GEMM below
        float xreg[XCNT];
        const bool have_next = (s + 1 < TSEQ);
        if (have_next) {
            const int tn = fwd ? (s + 1) : (TSEQ - 2 - s);
            const float* inb = inb0 + (size_t)tn * D;
#pragma unroll
            for (int c = 0; c < XCNT; c++)
                if (c < NC) xreg[c] = inb[goff[c]];
        }

        float acc[BPT][8];
#pragma unroll
        for (int bi = 0; bi < BPT; bi++)
#pragma unroll
            for (int q = 0; q < 8; q++) acc[bi][q] = bj[q];

        // z += x_t @ Wk
#pragma unroll 4
        for (int k = 0; k < D; k++) {
            float4 w0 = *(const float4*)(wk + k * NG);
            float4 w1 = *(const float4*)(wk + k * NG + 4);
#pragma unroll
            for (int bi = 0; bi < BPT; bi++) {
                float v = sXc[(tb * BPT + bi) * DS + k];
                acc[bi][0] = fmaf(v, w0.x, acc[bi][0]);
                acc[bi][1] = fmaf(v, w0.y, acc[bi][1]);
                acc[bi][2] = fmaf(v, w0.z, acc[bi][2]);
                acc[bi][3] = fmaf(v, w0.w, acc[bi][3]);
                acc[bi][4] = fmaf(v, w1.x, acc[bi][4]);
                acc[bi][5] = fmaf(v, w1.y, acc[bi][5]);
                acc[bi][6] = fmaf(v, w1.z, acc[bi][6]);
                acc[bi][7] = fmaf(v, w1.w, acc[bi][7]);
            }
        }
        // z += h_{t-1} @ Wr
#pragma unroll 4
        for (int k = 0; k < H; k++) {
            float4 w0 = *(const float4*)(wr + k * NG);
            float4 w1 = *(const float4*)(wr + k * NG + 4);
#pragma unroll
            for (int bi = 0; bi < BPT; bi++) {
                float v = sHc[(tb * BPT + bi) * HS + k];
                acc[bi][0] = fmaf(v, w0.x, acc[bi][0]);
                acc[bi][1] = fmaf(v, w0.y, acc[bi][1]);
                acc[bi][2] = fmaf(v, w0.z, acc[bi][2]);
                acc[bi][3] = fmaf(v, w0.w, acc[bi][3]);
                acc[bi][4] = fmaf(v, w1.x, acc[bi][4]);
                acc[bi][5] = fmaf(v, w1.y, acc[bi][5]);
                acc[bi][6] = fmaf(v, w1.z, acc[bi][6]);
                acc[bi][7] = fmaf(v, w1.w, acc[bi][7]);
            }
        }

        // drain staged x into the next buffer (no one reads sX[nxt] this step)
        if (have_next) {
            float* sXn = sX + nxt * BT * DS;
#pragma unroll
            for (int c = 0; c < XCNT; c++)
                if (c < NC) sXn[soff[c]] = xreg[c];
        }

        // gates: [i, f, g, o] per hidden unit; c in regs, h -> sH[nxt] + out
        {
            float* sHn = sH + nxt * BT * HS;
#pragma unroll
            for (int bi = 0; bi < BPT; bi++) {
                const int b = tb * BPT + bi;
                float h2[2];
#pragma unroll
                for (int jj = 0; jj < 2; jj++) {
                    float zi = acc[bi][jj * 4 + 0];
                    float zf = acc[bi][jj * 4 + 1];
                    float zg = acc[bi][jj * 4 + 2];
                    float zo = acc[bi][jj * 4 + 3];
                    float cc = fsig(zf) * cst[bi][jj] + fsig(zi) * ftanh(zg);
                    cst[bi][jj] = cc;
                    h2[jj] = fsig(zo) * ftanh(cc);
                    sHn[b * HS + jh0 + jj] = h2[jj];
                }
                float2 hv = make_float2(h2[0], h2[1]);
                *(float2*)(out + ((size_t)(b0 + b) * TSEQ + t) * (2 * H)
                               + (fwd ? 0 : H) + jh0) = hv;
            }
        }
        __syncthreads();   // single barrier: everything published for step s+1
    }
}

// Layer 4 (D=32, H=4, return final state only).
// 4 threads per (row, direction): thread handles ONE hidden unit (4 gate cols).
// h exchanged across the lane-quad with __shfl_sync; c scalar in register.
// x double-buffered in registers. No __syncthreads in the time loop.
__global__ void __launch_bounds__(128)
lstm_l4(const float* __restrict__ WkF, const float* __restrict__ WrF, const float* __restrict__ bF,
        const float* __restrict__ WkB, const float* __restrict__ WrB, const float* __restrict__ bB)
{
    const float* in = d_seq1;        // L3 output, [B][T][32]
    const int tid  = threadIdx.x;
    const int unit = tid & 3;
    const int rl   = tid >> 2;       // 0..31
    const int lane = tid & 31;
    const bool fwd = (blockIdx.y == 0);
    const int row  = blockIdx.x * 32 + rl;

    __shared__ alignas(16) float sWk[32 * 16];   // permuted [k][j*4+g]
    __shared__ alignas(16) float sWr[4 * 16];
    __shared__ alignas(16) float sB[16];

    const float* Wk = fwd ? WkF : WkB;
    const float* Wr = fwd ? WrF : WrB;
    const float* bv = fwd ? bF  : bB;

    for (int i = tid; i < 32 * 16; i += 128) {
        int k = i >> 4, col = i & 15;
        sWk[i] = Wk[k * 16 + (col & 3) * 4 + (col >> 2)];
    }
    if (tid < 4 * 16) {
        int k = tid >> 4, col = tid & 15;
        sWr[tid] = Wr[k * 16 + (col & 3) * 4 + (col >> 2)];
    }
    if (tid < 16) sB[tid] = bv[(tid & 3) * 4 + (tid >> 2)];
    __syncthreads();

    float bz[4];
#pragma unroll
    for (int q = 0; q < 4; q++) bz[q] = sB[unit * 4 + q];

    float h = 0.0f, c = 0.0f;

    const float* base = in + (size_t)row * TSEQ * 32;
    float4 xa[8], xb[8];
    {
        const float4* p = (const float4*)(base + (fwd ? 0 : (TSEQ - 1)) * 32);
#pragma unroll
        for (int i = 0; i < 8; i++) xa[i] = p[i];
    }

#pragma unroll 1
    for (int s = 0; s < TSEQ; s++) {
        if (s + 1 < TSEQ) {
            const int tn = fwd ? (s + 1) : (TSEQ - 2 - s);
            const float4* p = (const float4*)(base + tn * 32);
#pragma unroll
            for (int i = 0; i < 8; i++) xb[i] = p[i];
        }

        float z[4];
#pragma unroll
        for (int q = 0; q < 4; q++) z[q] = bz[q];

#pragma unroll
        for (int k = 0; k < 32; k++) {
            float v = ((const float*)xa)[k];
            float4 w = *(const float4*)(sWk + k * 16 + unit * 4);
            z[0] = fmaf(v, w.x, z[0]);
            z[1] = fmaf(v, w.y, z[1]);
            z[2] = fmaf(v, w.z, z[2]);
            z[3] = fmaf(v, w.w, z[3]);
        }
#pragma unroll
        for (int k = 0; k < 4; k++) {
            float hk = __shfl_sync(0xffffffffu, h, (lane & ~3) + k, 32);
            float4 w = *(const float4*)(sWr + k * 16 + unit * 4);
            z[0] = fmaf(hk, w.x, z[0]);
            z[1] = fmaf(hk, w.y, z[1]);
            z[2] = fmaf(hk, w.z, z[2]);
            z[3] = fmaf(hk, w.w, z[3]);
        }

        float cc = fsig(z[1]) * c + fsig(z[0]) * ftanh(z[2]);
        c = cc;
        h = fsig(z[3]) * ftanh(cc);

#pragma unroll
        for (int i = 0; i < 8; i++) xa[i] = xb[i];
    }

    d_h4[(size_t)row * 8 + (fwd ? 0 : 4) + unit] = h;
}

__global__ void dense_sig(const float* __restrict__ W,
                          const float* __restrict__ bb, float* __restrict__ out)
{
    int b = blockIdx.x * blockDim.x + threadIdx.x;
    if (b >= BATCH) return;
    const float* hr = d_h4 + (size_t)b * 8;
    float hv[8];
#pragma unroll
    for (int j = 0; j < 8; j++) hv[j] = hr[j];
#pragma unroll
    for (int m = 0; m < 3; m++) {
        float a = bb[m];
#pragma unroll
        for (int j = 0; j < 8; j++) a = fmaf(hv[j], W[j * 3 + m], a);
        out[(size_t)b * 3 + m] = fsig(a);
    }
}

static size_t smem_bytes(int D, int H, int BT) {
    int NG = 4 * H;
    int DS = (D % 2 == 0) ? D + 1 : D;
    int HS = H + 1;
    return (size_t)(D * NG + H * NG + NG + 2 * BT * HS + 2 * BT * DS) * sizeof(float);
}

extern "C" void kernel_launch(void* const* d_in, const int* in_sizes, int n_in,
                              void* d_out, int out_size)
{
    (void)in_sizes; (void)n_in; (void)out_size;
    float* x = (float*)d_in[0];
    const float* p[24];
    for (int i = 0; i < 24; i++) p[i] = (const float*)d_in[1 + i];
    const float* dW = (const float*)d_in[25];
    const float* db = (const float*)d_in[26];

    size_t s1 = smem_bytes(78, 64, 64);
    size_t s2 = smem_bytes(128, 32, 64);
    size_t s3 = smem_bytes(64, 16, 64);
    cudaFuncSetAttribute(lstm_layer<78, 64, 64, 8, 0, 1>,
                         cudaFuncAttributeMaxDynamicSharedMemorySize, (int)s1);
    cudaFuncSetAttribute(lstm_layer<128, 32, 64, 4, 1, 2>,
                         cudaFuncAttributeMaxDynamicSharedMemorySize, (int)s2);
    cudaFuncSetAttribute(lstm_layer<64, 16, 64, 2, 2, 3>,
                         cudaFuncAttributeMaxDynamicSharedMemorySize, (int)s3);

    // L1: x -> seq1 (78 -> 2*64), grid (64,2), 256 thr
    lstm_layer<78, 64, 64, 8, 0, 1><<<dim3(BATCH / 64, 2), 256, s1>>>(
        x, nullptr, p[0], p[1], p[2], p[3], p[4], p[5]);
    // L2: seq1 -> seq2 (128 -> 2*32)
    lstm_layer<128, 32, 64, 4, 1, 2><<<dim3(BATCH / 64, 2), 256, s2>>>(
        nullptr, nullptr, p[6], p[7], p[8], p[9], p[10], p[11]);
    // L3: seq2 -> seq3(=seq1 front) (64 -> 2*16)
    lstm_layer<64, 16, 64, 2, 2, 3><<<dim3(BATCH / 64, 2), 256, s3>>>(
        nullptr, nullptr, p[12], p[13], p[14], p[15], p[16], p[17]);
    // L4: seq3 -> h4 final states [B,8], 4 threads/row, shuffle-coupled
    lstm_l4<<<dim3(BATCH / 32, 2), 128>>>(p[18], p[19], p[20], p[21], p[22], p[23]);
    // dense 8->3 + sigmoid
    dense_sig<<<(BATCH + 255) / 256, 256>>>(dW, db, (float*)d_out);
}

// round 17
// speedup vs baseline: 1.4792x; 1.0059x over previous
#include <cuda_runtime.h>
#include <cuda_bf16.h>
#include <mma.h>

using namespace nvcuda;
using namespace wmma;

// Style rules for this bench pipeline (hard-won): no function-like macros, no
// backslash escapes anywhere, no inline asm, no double-colon tokens.
constexpr int    TSEQ  = 128;
constexpr int    BATCH = 4096;
constexpr size_t NROWS = (size_t)BATCH * TSEQ;   // 524288 flattened (b,t) rows

// ---------------- static device buffers (no allocation anywhere) -------------
// g_hi/g_lo: bf16 hi/lo activations. Stride 80 for x (L1, K padded 78->80),
// then 128 (rec1 out, feeds L2), then 64 (rec2 out, feeds L3).
__device__ __align__(256) __nv_bfloat16 g_hi[NROWS * 128];
__device__ __align__(256) __nv_bfloat16 g_lo[NROWS * 128];
__device__ __align__(256) float g_xz[NROWS * 512];   // gate pre-activations
__device__ __align__(256) float d_seq3[NROWS * 32];  // L3 output (fp32)
__device__ float d_h4[BATCH * 8];
__device__ __align__(256) __nv_bfloat16 g_whi[512 * 128];  // permuted split W
__device__ __align__(256) __nv_bfloat16 g_wlo[512 * 128];
__device__ float g_bperm[512];

__device__ __forceinline__ float fsig(float x) { return 1.0f / (1.0f + __expf(-x)); }
__device__ __forceinline__ float ftanh(float x) {
    float e = __expf(2.0f * x);
    return 1.0f - 2.0f / (e + 1.0f);
}

// ---------------- conv: x fp32 to bf16 hi/lo, K padded 78 -> 80 --------------
__global__ void conv_x(const float* __restrict__ x) {
    size_t idx = (size_t)blockIdx.x * blockDim.x + threadIdx.x;
    if (idx >= NROWS * 80) return;
    size_t row = idx / 80;
    int k = (int)(idx - row * 80);
    float v = (k < 78) ? x[row * 78 + k] : 0.0f;
    __nv_bfloat16 h = __float2bfloat16(v);
    g_hi[idx] = h;
    g_lo[idx] = __float2bfloat16(v - __bfloat162float(h));
}

// ---------------- weight prep: permuted, transposed, split, padded -----------
// Output row s in [0, 2NG): first NG = fwd, rest = bwd. Within a half, slot s2
// maps to original column (s2 mod 4)*H + (s2 div 4) so gates interleave i,f,g,o
// per hidden unit. Row-major [s][KP], k >= D zero-padded.
template<int D, int H, int KP>
__global__ void wprep(const float* __restrict__ Wf, const float* __restrict__ Wb,
                      const float* __restrict__ bf, const float* __restrict__ bb) {
    constexpr int NG = 4 * H;
    int idx = blockIdx.x * blockDim.x + threadIdx.x;
    if (idx >= 2 * NG * KP) return;
    int s = idx / KP, k = idx - s * KP;
    int s2 = (s < NG) ? s : s - NG;
    const float* W = (s < NG) ? Wf : Wb;
    const float* bv = (s < NG) ? bf : bb;
    int orig = (s2 & 3) * H + (s2 >> 2);
    float v = (k < D) ? W[k * NG + orig] : 0.0f;
    __nv_bfloat16 h = __float2bfloat16(v);
    g_whi[s * KP + k] = h;
    g_wlo[s * KP + k] = __float2bfloat16(v - __bfloat162float(h));
    if (k == 0) g_bperm[s] = bv[orig];
}

// ---------------- wmma bf16-split GEMM: xz = act @ W transposed --------------
// Grid NROWS/64 CTAs of 128 threads (4 warps). Warp w owns 16 rows. All
// fragments loaded straight from global (A rows are L1-resident across the
// column loop; B is shared by all CTAs and stays L2-hot). Split arithmetic:
// acc += Ah*Bh + Al*Bh + Ah*Bl with fp32 accumulators (residual ~2^-16).
// Bias is NOT added here (rec adds it from g_bperm).
template<int KP, int NG2>
__global__ void __launch_bounds__(128) gemm_xz() {
    const int wid = threadIdx.x >> 5;
    const size_t m0 = (size_t)blockIdx.x * 64 + (size_t)wid * 16;
    const __nv_bfloat16* Ah = g_hi + m0 * KP;
    const __nv_bfloat16* Al = g_lo + m0 * KP;

    fragment<matrix_a, 16, 16, 16, __nv_bfloat16, row_major> fah;
    fragment<matrix_a, 16, 16, 16, __nv_bfloat16, row_major> fal;
    fragment<matrix_b, 16, 16, 16, __nv_bfloat16, col_major> fb;
    fragment<accumulator, 16, 16, 16, float> acc0, acc1, acc2, acc3;

    for (int cg = 0; cg < NG2; cg += 64) {
        fill_fragment(acc0, 0.0f);
        fill_fragment(acc1, 0.0f);
        fill_fragment(acc2, 0.0f);
        fill_fragment(acc3, 0.0f);
        for (int k0 = 0; k0 < KP; k0 += 16) {
            load_matrix_sync(fah, Ah + k0, KP);
            load_matrix_sync(fal, Al + k0, KP);

            const __nv_bfloat16* b0h = g_whi + (size_t)(cg + 0)  * KP + k0;
            const __nv_bfloat16* b1h = g_whi + (size_t)(cg + 16) * KP + k0;
            const __nv_bfloat16* b2h = g_whi + (size_t)(cg + 32) * KP + k0;
            const __nv_bfloat16* b3h = g_whi + (size_t)(cg + 48) * KP + k0;
            const __nv_bfloat16* b0l = g_wlo + (size_t)(cg + 0)  * KP + k0;
            const __nv_bfloat16* b1l = g_wlo + (size_t)(cg + 16) * KP + k0;
            const __nv_bfloat16* b2l = g_wlo + (size_t)(cg + 32) * KP + k0;
            const __nv_bfloat16* b3l = g_wlo + (size_t)(cg + 48) * KP + k0;

            load_matrix_sync(fb, b0h, KP);
            mma_sync(acc0, fah, fb, acc0);
            mma_sync(acc0, fal, fb, acc0);
            load_matrix_sync(fb, b0l, KP);
            mma_sync(acc0, fah, fb, acc0);

            load_matrix_sync(fb, b1h, KP);
            mma_sync(acc1, fah, fb, acc1);
            mma_sync(acc1, fal, fb, acc1);
            load_matrix_sync(fb, b1l, KP);
            mma_sync(acc1, fah, fb, acc1);

            load_matrix_sync(fb, b2h, KP);
            mma_sync(acc2, fah, fb, acc2);
            mma_sync(acc2, fal, fb, acc2);
            load_matrix_sync(fb, b2l, KP);
            mma_sync(acc2, fah, fb, acc2);

            load_matrix_sync(fb, b3h, KP);
            mma_sync(acc3, fah, fb, acc3);
            mma_sync(acc3, fal, fb, acc3);
            load_matrix_sync(fb, b3l, KP);
            mma_sync(acc3, fah, fb, acc3);
        }
        float* dst = g_xz + m0 * NG2 + cg;
        store_matrix_sync(dst + 0,  acc0, NG2, mem_row_major);
        store_matrix_sync(dst + 16, acc1, NG2, mem_row_major);
        store_matrix_sync(dst + 32, acc2, NG2, mem_row_major);
        store_matrix_sync(dst + 48, acc3, NG2, mem_row_major);
    }
}

// ---------------- recurrent layers 1-3: z = xz[t] + bias + h @ Wr ------------
// R8-proven skeleton; input-projection loop removed (acc init = prefetched xz,
// bias added at gate evaluation from g_bperm). OUTF32=0 emits bf16 hi/lo for
// the next GEMM; OUTF32=1 emits fp32 seq3 for L4.
template<int H, int BT, int BPT, int OUTF32>
__global__ void __launch_bounds__((H / 2) * (BT / BPT))
rec_layer(const float* __restrict__ WrF, const float* __restrict__ WrB)
{
    constexpr int NG = 4 * H;
    constexpr int TJ = NG / 8;
    constexpr int TB = BT / BPT;
    constexpr int NT = TJ * TB;
    constexpr int HS = H + 1;
    constexpr int XSTR = 2 * NG;
    constexpr int OSTR = 2 * H;

    extern __shared__ float sm[];
    float* sWr = sm;                 // [H][NG] permuted
    float* sH  = sWr + H * NG;       // 2 x [BT][HS]

    const int tid = threadIdx.x;
    const int tj  = tid % TJ;
    const int tb  = tid / TJ;
    const bool fwd = (blockIdx.y == 0);
    const int dir = fwd ? 0 : 1;
    const float* Wr = fwd ? WrF : WrB;
    const int b0 = blockIdx.x * BT;

    for (int i = tid; i < H * NG; i += NT) {
        int k = i / NG, col = i - k * NG;
        sWr[i] = Wr[k * NG + (col & 3) * H + (col >> 2)];
    }
    for (int i = tid; i < 2 * BT * HS; i += NT) sH[i] = 0.0f;
    __syncthreads();

    float bj[8];
#pragma unroll
    for (int q = 0; q < 8; q++) bj[q] = g_bperm[dir * NG + tj * 8 + q];

    float cst[BPT][2];
#pragma unroll
    for (int bi = 0; bi < BPT; bi++) { cst[bi][0] = 0.0f; cst[bi][1] = 0.0f; }

    const int jh0 = tj * 2;
    const float* wr = sWr + tj * 8;
    const float* xzb = g_xz + (size_t)dir * NG + (size_t)tj * 8;

    float xzc[BPT][8];
    {
        const int t0 = fwd ? 0 : (TSEQ - 1);
#pragma unroll
        for (int bi = 0; bi < BPT; bi++) {
            size_t m = (size_t)(b0 + tb * BPT + bi) * TSEQ + t0;
            const float* p = xzb + m * XSTR;
            *(float4*)&xzc[bi][0] = *(const float4*)p;
            *(float4*)&xzc[bi][4] = *(const float4*)(p + 4);
        }
    }

    for (int s = 0; s < TSEQ; s++) {
        const int t   = fwd ? s : (TSEQ - 1 - s);
        const int cur = s & 1;
        const int nxt = cur ^ 1;
        const float* sHc = sH + cur * BT * HS;

        float xzn[BPT][8];
        const bool have_next = (s + 1 < TSEQ);
        if (have_next) {
            const int tn = fwd ? (s + 1) : (TSEQ - 2 - s);
#pragma unroll
            for (int bi = 0; bi < BPT; bi++) {
                size_t m = (size_t)(b0 + tb * BPT + bi) * TSEQ + tn;
                const float* p = xzb + m * XSTR;
                *(float4*)&xzn[bi][0] = *(const float4*)p;
                *(float4*)&xzn[bi][4] = *(const float4*)(p + 4);
            }
        }

#pragma unroll 4
        for (int k = 0; k < H; k++) {
            float4 w0 = *(const float4*)(wr + k * NG);
            float4 w1 = *(const float4*)(wr + k * NG + 4);
#pragma unroll
            for (int bi = 0; bi < BPT; bi++) {
                float v = sHc[(tb * BPT + bi) * HS + k];
                xzc[bi][0] = fmaf(v, w0.x, xzc[bi][0]);
                xzc[bi][1] = fmaf(v, w0.y, xzc[bi][1]);
                xzc[bi][2] = fmaf(v, w0.z, xzc[bi][2]);
                xzc[bi][3] = fmaf(v, w0.w, xzc[bi][3]);
                xzc[bi][4] = fmaf(v, w1.x, xzc[bi][4]);
                xzc[bi][5] = fmaf(v, w1.y, xzc[bi][5]);
                xzc[bi][6] = fmaf(v, w1.z, xzc[bi][6]);
                xzc[bi][7] = fmaf(v, w1.w, xzc[bi][7]);
            }
        }

        {
            float* sHn = sH + nxt * BT * HS;
#pragma unroll
            for (int bi = 0; bi < BPT; bi++) {
                const int b = tb * BPT + bi;
                float h2[2];
#pragma unroll
                for (int jj = 0; jj < 2; jj++) {
                    float zi = xzc[bi][jj * 4 + 0] + bj[jj * 4 + 0];
                    float zf = xzc[bi][jj * 4 + 1] + bj[jj * 4 + 1];
                    float zg = xzc[bi][jj * 4 + 2] + bj[jj * 4 + 2];
                    float zo = xzc[bi][jj * 4 + 3] + bj[jj * 4 + 3];
                    float cc = fsig(zf) * cst[bi][jj] + fsig(zi) * ftanh(zg);
                    cst[bi][jj] = cc;
                    h2[jj] = fsig(zo) * ftanh(cc);
                    sHn[b * HS + jh0 + jj] = h2[jj];
                }
                size_t mo = (size_t)(b0 + b) * TSEQ + t;
                if (OUTF32) {
                    float2 ho = make_float2(h2[0], h2[1]);
                    *(float2*)(d_seq3 + mo * OSTR + dir * H + jh0) = ho;
                } else {
                    __nv_bfloat16 h0 = __float2bfloat16(h2[0]);
                    __nv_bfloat16 h1 = __float2bfloat16(h2[1]);
                    __nv_bfloat16 l0 = __float2bfloat16(h2[0] - __bfloat162float(h0));
                    __nv_bfloat16 l1 = __float2bfloat16(h2[1] - __bfloat162float(h1));
                    __nv_bfloat16* ph = g_hi + mo * OSTR + dir * H + jh0;
                    __nv_bfloat16* pl = g_lo + mo * OSTR + dir * H + jh0;
                    ph[0] = h0;
                    ph[1] = h1;
                    pl[0] = l0;
                    pl[1] = l1;
                }
            }
        }
#pragma unroll
        for (int bi = 0; bi < BPT; bi++)
#pragma unroll
            for (int q = 0; q < 8; q++) xzc[bi][q] = xzn[bi][q];
        __syncthreads();
    }
}

// ---------------- Layer 4 (proven 98us kernel) + dense -----------------------
__global__ void __launch_bounds__(128)
lstm_l4(const float* __restrict__ WkF, const float* __restrict__ WrF,
        const float* __restrict__ bF, const float* __restrict__ WkB,
        const float* __restrict__ WrB, const float* __restrict__ bB)
{
    const float* in = d_seq3;
    const int tid  = threadIdx.x;
    const int unit = tid & 3;
    const int rl   = tid >> 2;
    const int lane = tid & 31;
    const bool fwd = (blockIdx.y == 0);
    const int row  = blockIdx.x * 32 + rl;

    __shared__ alignas(16) float sWk[32 * 16];
    __shared__ alignas(16) float sWr[4 * 16];
    __shared__ alignas(16) float sB[16];

    const float* Wk = fwd ? WkF : WkB;
    const float* Wr = fwd ? WrF : WrB;
    const float* bv = fwd ? bF  : bB;

    for (int i = tid; i < 32 * 16; i += 128) {
        int k = i >> 4, col = i & 15;
        sWk[i] = Wk[k * 16 + (col & 3) * 4 + (col >> 2)];
    }
    if (tid < 4 * 16) {
        int k = tid >> 4, col = tid & 15;
        sWr[tid] = Wr[k * 16 + (col & 3) * 4 + (col >> 2)];
    }
    if (tid < 16) sB[tid] = bv[(tid & 3) * 4 + (tid >> 2)];
    __syncthreads();

    float bz[4];
#pragma unroll
    for (int q = 0; q < 4; q++) bz[q] = sB[unit * 4 + q];

    float h = 0.0f, c = 0.0f;
    const float* base = in + (size_t)row * TSEQ * 32;
    float4 xa[8], xb[8];
    {
        const float4* p = (const float4*)(base + (fwd ? 0 : (TSEQ - 1)) * 32);
#pragma unroll
        for (int i = 0; i < 8; i++) xa[i] = p[i];
    }

#pragma unroll 1
    for (int s = 0; s < TSEQ; s++) {
        if (s + 1 < TSEQ) {
            const int tn = fwd ? (s + 1) : (TSEQ - 2 - s);
            const float4* p = (const float4*)(base + tn * 32);
#pragma unroll
            for (int i = 0; i < 8; i++) xb[i] = p[i];
        }
        float z[4];
#pragma unroll
        for (int q = 0; q < 4; q++) z[q] = bz[q];
#pragma unroll
        for (int k = 0; k < 32; k++) {
            float v = ((const float*)xa)[k];
            float4 w = *(const float4*)(sWk + k * 16 + unit * 4);
            z[0] = fmaf(v, w.x, z[0]);
            z[1] = fmaf(v, w.y, z[1]);
            z[2] = fmaf(v, w.z, z[2]);
            z[3] = fmaf(v, w.w, z[3]);
        }
#pragma unroll
        for (int k = 0; k < 4; k++) {
            float hk = __shfl_sync(0xffffffffu, h, (lane & ~3) + k, 32);
            float4 w = *(const float4*)(sWr + k * 16 + unit * 4);
            z[0] = fmaf(hk, w.x, z[0]);
            z[1] = fmaf(hk, w.y, z[1]);
            z[2] = fmaf(hk, w.z, z[2]);
            z[3] = fmaf(hk, w.w, z[3]);
        }
        float cc = fsig(z[1]) * c + fsig(z[0]) * ftanh(z[2]);
        c = cc;
        h = fsig(z[3]) * ftanh(cc);
#pragma unroll
        for (int i = 0; i < 8; i++) xa[i] = xb[i];
    }
    d_h4[(size_t)row * 8 + (fwd ? 0 : 4) + unit] = h;
}

__global__ void dense_sig(const float* __restrict__ W,
                          const float* __restrict__ bb, float* __restrict__ out)
{
    int b = blockIdx.x * blockDim.x + threadIdx.x;
    if (b >= BATCH) return;
    const float* hr = d_h4 + (size_t)b * 8;
    float hv[8];
#pragma unroll
    for (int j = 0; j < 8; j++) hv[j] = hr[j];
#pragma unroll
    for (int m = 0; m < 3; m++) {
        float a = bb[m];
#pragma unroll
        for (int j = 0; j < 8; j++) a = fmaf(hv[j], W[j * 3 + m], a);
        out[(size_t)b * 3 + m] = fsig(a);
    }
}

// ---------------- host orchestration ----------------------------------------
static size_t rec_smem(int H, int BT) {
    int NG = 4 * H, HS = H + 1;
    return (size_t)(H * NG + 2 * BT * HS) * sizeof(float);
}

extern "C" void kernel_launch(void* const* d_in, const int* in_sizes, int n_in,
                              void* d_out, int out_size)
{
    (void)in_sizes; (void)n_in; (void)out_size;
    const float* x = (const float*)d_in[0];
    const float* p[24];
    for (int i = 0; i < 24; i++) p[i] = (const float*)d_in[1 + i];
    const float* dW = (const float*)d_in[25];
    const float* db = (const float*)d_in[26];

    size_t r1 = rec_smem(64, 64), r2 = rec_smem(32, 64), r3 = rec_smem(16, 64);
    cudaFuncSetAttribute(rec_layer<64, 64, 8, 0>,
                         cudaFuncAttributeMaxDynamicSharedMemorySize, (int)r1);
    cudaFuncSetAttribute(rec_layer<32, 64, 4, 0>,
                         cudaFuncAttributeMaxDynamicSharedMemorySize, (int)r2);
    cudaFuncSetAttribute(rec_layer<16, 64, 2, 1>,
                         cudaFuncAttributeMaxDynamicSharedMemorySize, (int)r3);

    const int GT = (int)(NROWS / 64);   // 8192 GEMM row tiles

    conv_x<<<(int)((NROWS * 80 + 255) / 256), 256>>>(x);
    // L1: GEMM (KP=80, 512 cols), then rec (H=64), bf16 out stride 128
    wprep<78, 64, 80><<<(512 * 80 + 255) / 256, 256>>>(p[0], p[3], p[2], p[5]);
    gemm_xz<80, 512><<<GT, 128>>>();
    rec_layer<64, 64, 8, 0><<<dim3(BATCH / 64, 2), 256, r1>>>(p[1], p[4]);
    // L2: GEMM (KP=128, 256 cols), then rec (H=32), bf16 out stride 64
    wprep<128, 32, 128><<<(256 * 128 + 255) / 256, 256>>>(p[6], p[9], p[8], p[11]);
    gemm_xz<128, 256><<<GT, 128>>>();
    rec_layer<32, 64, 4, 0><<<dim3(BATCH / 64, 2), 256, r2>>>(p[7], p[10]);
    // L3: GEMM (KP=64, 128 cols), then rec (H=16), fp32 seq3
    wprep<64, 16, 64><<<(128 * 64 + 255) / 256, 256>>>(p[12], p[15], p[14], p[17]);
    gemm_xz<64, 128><<<GT, 128>>>();
    rec_layer<16, 64, 2, 1><<<dim3(BATCH / 64, 2), 256, r3>>>(p[13], p[16]);
    // L4 + dense
    lstm_l4<<<dim3(BATCH / 32, 2), 128>>>(p[18], p[19], p[20], p[21], p[22], p[23]);
    dense_sig<<<(BATCH + 255) / 256, 256>>>(dW, db, (float*)d_out);
}